// round 1
// baseline (speedup 1.0000x reference)
#include <cuda_runtime.h>

// Bidirectional tanh-Elman RNN, B=32, S=2048, D=H=256, fp32.
// Persistent kernel: 128 CTAs (64/direction), device-wide spin barrier per step.
// Each CTA owns a 16-column slice of Wh & Wx (smem-resident) and 8 batch rows.
// h state ping-pongs through L2 (ldcg/stcg; L1 is not coherent across SMs).

#define B_SZ 32
#define S_SZ 2048
#define D_SZ 256
#define H_SZ 256

#define NBLK_DIR 64      // blocks per direction
#define JT 16            // columns per block
#define BT 8             // batch rows per block

// persistent device state (allowed: __device__ globals, no allocation)
__device__ float g_h[2][2][B_SZ * H_SZ];   // [dir][parity][b*H + j]
__device__ unsigned g_bar[2];              // per-direction barrier counters

__global__ void reset_kernel() {
    int gid = blockIdx.x * blockDim.x + threadIdx.x;
    if (gid < 2 * B_SZ * H_SZ) {
        int dir = gid / (B_SZ * H_SZ);
        g_h[dir][0][gid % (B_SZ * H_SZ)] = 0.0f;
    }
    if (gid < 2) g_bar[gid] = 0u;
}

// dynamic smem layout (floats):
//   sWh  [0,     4096)   Wh[:, j0:j0+16]   row i * 16 + jt
//   sWx  [4096,  8192)   Wx[:, j0:j0+16]
//   sRed [8192,  9216)   float4[256] k-partials
//   sH   [9216, 11520)   h transposed, pitch 9: sH[i*9 + b]
//   sX   [11520,13824)   x_t transposed, pitch 9
//   sB   [13824,13840)   bias slice
#define SMEM_FLOATS 13840
#define SMEM_BYTES  (SMEM_FLOATS * 4)

__global__ __launch_bounds__(256, 1) void rnn_kernel(
    const float* __restrict__ x,
    const float* __restrict__ Wx_f, const float* __restrict__ Wh_f, const float* __restrict__ b_f,
    const float* __restrict__ Wx_b, const float* __restrict__ Wh_b, const float* __restrict__ b_b,
    float* __restrict__ out)
{
    extern __shared__ float sm[];
    float* sWh  = sm;
    float* sWx  = sm + 4096;
    float* sRed = sm + 8192;
    float* sH   = sm + 9216;
    float* sX   = sm + 11520;
    float* sB   = sm + 13824;

    const int t   = threadIdx.x;
    const int dir = blockIdx.x >> 6;        // 0 = fwd, 1 = bwd
    const int blk = blockIdx.x & 63;
    const int j0  = (blk & 15) << 4;        // 16 j-slices of 16 cols
    const int b0  = (blk >> 4) << 3;        // 4 b-slices of 8 rows

    const float* Wx   = dir ? Wx_b : Wx_f;
    const float* Wh   = dir ? Wh_b : Wh_f;
    const float* bias = dir ? b_b  : b_f;

    // preload weight slices into smem (once)
    for (int idx = t; idx < 4096; idx += 256) {
        int i = idx >> 4, jt = idx & 15;
        sWh[idx] = Wh[i * H_SZ + j0 + jt];
        sWx[idx] = Wx[i * H_SZ + j0 + jt];
    }
    if (t < 16) sB[t] = bias[j0 + t];
    __syncthreads();

    // compute-thread coordinates: 4 j-quad x 8 batch x 8 k-chunks
    const int jq  = t & 3;           // j-quad (4 cols via float4)
    const int bb  = (t >> 2) & 7;    // batch row within slice
    const int kk  = t >> 5;          // k-chunk (warp id)
    const int ib  = kk << 5;         // 32 i's per chunk

    for (int s = 0; s < S_SZ; ++s) {
        const int sx = dir ? (S_SZ - 1 - s) : s;

        // stage h (L2, coherent via ldcg) and x_t into smem, transposed [i][b] pitch 9
        const float* hsrc = g_h[dir][s & 1];
        #pragma unroll
        for (int r = 0; r < 2; ++r) {
            int q  = t + (r << 8);        // 0..511 quads
            int b  = q >> 6;              // 0..7
            int iq = (q & 63) << 2;       // 0..252
            float4 hv = __ldcg((const float4*)(hsrc + (b0 + b) * H_SZ + iq));
            sH[(iq + 0) * 9 + b] = hv.x;
            sH[(iq + 1) * 9 + b] = hv.y;
            sH[(iq + 2) * 9 + b] = hv.z;
            sH[(iq + 3) * 9 + b] = hv.w;
            float4 xv = *(const float4*)(x + ((size_t)(b0 + b) * S_SZ + sx) * D_SZ + iq);
            sX[(iq + 0) * 9 + b] = xv.x;
            sX[(iq + 1) * 9 + b] = xv.y;
            sX[(iq + 2) * 9 + b] = xv.z;
            sX[(iq + 3) * 9 + b] = xv.w;
        }
        __syncthreads();

        // partial dot products: acc[j] = sum_{i in chunk} h[b][i]*Wh[i][j] + x[b][i]*Wx[i][j]
        float4 acc = make_float4(0.f, 0.f, 0.f, 0.f);
        #pragma unroll
        for (int ii = 0; ii < 32; ++ii) {
            int i = ib + ii;
            float  hv = sH[i * 9 + bb];
            float4 w  = *(const float4*)(sWh + (i << 4) + (jq << 2));
            acc.x = fmaf(hv, w.x, acc.x);
            acc.y = fmaf(hv, w.y, acc.y);
            acc.z = fmaf(hv, w.z, acc.z);
            acc.w = fmaf(hv, w.w, acc.w);
        }
        #pragma unroll
        for (int ii = 0; ii < 32; ++ii) {
            int i = ib + ii;
            float  xv = sX[i * 9 + bb];
            float4 w  = *(const float4*)(sWx + (i << 4) + (jq << 2));
            acc.x = fmaf(xv, w.x, acc.x);
            acc.y = fmaf(xv, w.y, acc.y);
            acc.z = fmaf(xv, w.z, acc.z);
            acc.w = fmaf(xv, w.w, acc.w);
        }
        ((float4*)sRed)[t] = acc;
        __syncthreads();

        // reduce 8 k-partials, add bias, tanh, write h_next + output
        if (t < 128) {
            int jt = t & 15;
            int b  = t >> 4;
            float sum = sB[jt];
            #pragma unroll
            for (int k = 0; k < 8; ++k)
                sum += sRed[jt + (b << 4) + (k << 7)];
            float hnew = tanhf(sum);
            __stcg(&g_h[dir][(s + 1) & 1][(b0 + b) * H_SZ + j0 + jt], hnew);
            out[((size_t)(b0 + b) * S_SZ + sx) * (2 * H_SZ) + dir * H_SZ + j0 + jt] = hnew;
        }

        // per-direction grid barrier (skip after last step)
        if (s + 1 < S_SZ) {
            __threadfence();
            __syncthreads();
            if (t == 0) {
                unsigned target = (unsigned)NBLK_DIR * (unsigned)(s + 1);
                atomicAdd(&g_bar[dir], 1u);
                while (atomicAdd(&g_bar[dir], 0u) < target)
                    __nanosleep(32);
                __threadfence();
            }
            __syncthreads();
        }
    }
}

extern "C" void kernel_launch(void* const* d_in, const int* in_sizes, int n_in,
                              void* d_out, int out_size)
{
    const float* x    = (const float*)d_in[0];
    const float* Wx_f = (const float*)d_in[1];
    const float* Wh_f = (const float*)d_in[2];
    const float* b_f  = (const float*)d_in[3];
    const float* Wx_b = (const float*)d_in[4];
    const float* Wh_b = (const float*)d_in[5];
    const float* b_b  = (const float*)d_in[6];
    float* out = (float*)d_out;

    cudaFuncSetAttribute(rnn_kernel, cudaFuncAttributeMaxDynamicSharedMemorySize, SMEM_BYTES);

    reset_kernel<<<16, 1024>>>();
    rnn_kernel<<<2 * NBLK_DIR, 256, SMEM_BYTES>>>(x, Wx_f, Wh_f, b_f, Wx_b, Wh_b, b_b, out);
}